// round 2
// baseline (speedup 1.0000x reference)
#include <cuda_runtime.h>
#include <cuda_bf16.h>

#define N_NODES 100000
#define N_EDGES 1600000
#define NUM_GRAPHS 4096
#define HID 128
#define F_IN 11
#define F_OUT 19

// ---------------- scratch (static device globals; no allocation) ----------------
__device__ int   g_cnt[N_NODES];          // in-degree (edges only)
__device__ int   g_fill[N_NODES];         // CSR fill cursors
__device__ float g_dinv[N_NODES];         // deg^-1/2 (deg includes self loop)
__device__ int   g_rowptr[N_NODES + 1];   // CSR row pointers (by dst)
__device__ int   g_csr_src[N_EDGES];      // src node per CSR slot
__device__ float g_csr_norm[N_EDGES];     // dinv[src]*dinv[dst] per CSR slot
__device__ float g_agg1[N_NODES * F_IN];  // layer-1 aggregated input features
__device__ float g_h1[N_NODES * HID];     // relu(agg1 @ W1 + b1)
__device__ float g_agg2[N_NODES * HID];   // layer-2 aggregated h1
__device__ float g_sums[NUM_GRAPHS * HID];
__device__ float g_gcnt[NUM_GRAPHS];

// ---------------- kernels ----------------

__global__ void k_zero() {
    int i = blockIdx.x * blockDim.x + threadIdx.x;
    int stride = gridDim.x * blockDim.x;
    for (int j = i; j < N_NODES; j += stride) { g_cnt[j] = 0; g_fill[j] = 0; }
    for (int j = i; j < NUM_GRAPHS * HID; j += stride) g_sums[j] = 0.f;
    for (int j = i; j < NUM_GRAPHS; j += stride) g_gcnt[j] = 0.f;
}

__global__ void k_count(const int* __restrict__ dst) {
    int i = blockIdx.x * blockDim.x + threadIdx.x;
    int stride = gridDim.x * blockDim.x;
    for (int e = i; e < N_EDGES; e += stride)
        atomicAdd(&g_cnt[dst[e]], 1);
}

__global__ void k_dinv() {
    int i = blockIdx.x * blockDim.x + threadIdx.x;
    if (i < N_NODES)
        g_dinv[i] = rsqrtf((float)(g_cnt[i] + 1));   // +1 self loop; deg >= 1 always
}

// single-block exclusive scan of g_cnt -> g_rowptr (N_NODES small enough)
__global__ void k_scan() {
    __shared__ int sm[1024];
    __shared__ int carry;
    int t = threadIdx.x;
    if (t == 0) carry = 0;
    __syncthreads();
    for (int base = 0; base < N_NODES; base += 1024) {
        int idx = base + t;
        int v = (idx < N_NODES) ? g_cnt[idx] : 0;
        sm[t] = v;
        __syncthreads();
        for (int off = 1; off < 1024; off <<= 1) {
            int add = (t >= off) ? sm[t - off] : 0;
            __syncthreads();
            sm[t] += add;
            __syncthreads();
        }
        if (idx < N_NODES) g_rowptr[idx] = carry + (sm[t] - v);   // exclusive
        __syncthreads();
        if (t == 0) carry += sm[1023];
        __syncthreads();
    }
    if (t == 0) g_rowptr[N_NODES] = carry;
}

__global__ void k_fill(const int* __restrict__ src, const int* __restrict__ dst) {
    int i = blockIdx.x * blockDim.x + threadIdx.x;
    int stride = gridDim.x * blockDim.x;
    for (int e = i; e < N_EDGES; e += stride) {
        int s = src[e], d = dst[e];
        int pos = g_rowptr[d] + atomicAdd(&g_fill[d], 1);
        g_csr_src[pos] = s;
        g_csr_norm[pos] = g_dinv[s] * g_dinv[d];
    }
}

// layer-1 aggregation on RAW inputs (11 features): agg1[i] = sum over in-edges + self
__global__ void k_agg1(const float* __restrict__ x) {
    int i = blockIdx.x * blockDim.x + threadIdx.x;
    if (i >= N_NODES) return;
    float di = g_dinv[i];
    float selfw = di * di;
    float acc[F_IN];
#pragma unroll
    for (int f = 0; f < F_IN; f++) acc[f] = x[i * F_IN + f] * selfw;
    int rs = g_rowptr[i], re = g_rowptr[i + 1];
    for (int e = rs; e < re; e++) {
        int s = g_csr_src[e];
        float w = g_csr_norm[e];
#pragma unroll
        for (int f = 0; f < F_IN; f++) acc[f] += x[s * F_IN + f] * w;
    }
#pragma unroll
    for (int f = 0; f < F_IN; f++) g_agg1[i * F_IN + f] = acc[f];
}

// h1 = relu(agg1 @ W1 + b1); one block per node, one thread per output channel
__global__ void k_gemm1(const float* __restrict__ W1, const float* __restrict__ b1) {
    int i = blockIdx.x;
    int f = threadIdx.x;
    __shared__ float sa[F_IN];
    if (f < F_IN) sa[f] = g_agg1[i * F_IN + f];
    __syncthreads();
    float acc = b1[f];
#pragma unroll
    for (int k = 0; k < F_IN; k++) acc = fmaf(sa[k], W1[k * HID + f], acc);
    g_h1[i * HID + f] = fmaxf(acc, 0.f);
}

// layer-2 aggregation of h1 (128-wide). One block (128 threads) per node.
__global__ void k_agg2() {
    int i = blockIdx.x;
    int f = threadIdx.x;
    float di = g_dinv[i];
    float acc = g_h1[i * HID + f] * di * di;
    int rs = g_rowptr[i], re = g_rowptr[i + 1];
    for (int e = rs; e < re; e++) {
        int s = g_csr_src[e];        // broadcast load across the block
        float w = g_csr_norm[e];
        acc = fmaf(g_h1[s * HID + f], w, acc);
    }
    g_agg2[i * HID + f] = acc;
}

// h2 = agg2 @ W2 + b2, fused with mean-pool accumulation (no h2 materialization)
__global__ void k_gemm2pool(const float* __restrict__ W2, const float* __restrict__ b2,
                            const int* __restrict__ batch) {
    int i = blockIdx.x;
    int f = threadIdx.x;
    __shared__ float sa[HID];
    sa[f] = g_agg2[i * HID + f];
    __syncthreads();
    float acc = b2[f];
#pragma unroll 8
    for (int k = 0; k < HID; k++) acc = fmaf(sa[k], W2[k * HID + f], acc);
    int g = batch[i];
    atomicAdd(&g_sums[g * HID + f], acc);
    if (f == 0) atomicAdd(&g_gcnt[g], 1.f);
}

// out = (sums / max(cnt,1)) @ Wlin + blin ; one block (32 threads) per graph
__global__ void k_final(const float* __restrict__ Wlin, const float* __restrict__ blin,
                        float* __restrict__ out) {
    int g = blockIdx.x;
    int o = threadIdx.x;
    __shared__ float sp[HID];
    for (int k = o; k < HID; k += 32) sp[k] = g_sums[g * HID + k];
    __syncthreads();
    float inv = 1.f / fmaxf(g_gcnt[g], 1.f);
    if (o < F_OUT) {
        float acc = blin[o];
#pragma unroll 8
        for (int k = 0; k < HID; k++) acc = fmaf(sp[k] * inv, Wlin[k * F_OUT + o], acc);
        out[g * F_OUT + o] = acc;
    }
}

// ---------------- launch ----------------
extern "C" void kernel_launch(void* const* d_in, const int* in_sizes, int n_in,
                              void* d_out, int out_size) {
    const float* x    = (const float*)d_in[0];
    const int*   esrc = (const int*)d_in[1];
    const int*   edst = (const int*)d_in[2];
    const int*   batch= (const int*)d_in[3];
    const float* W1   = (const float*)d_in[4];
    const float* b1   = (const float*)d_in[5];
    const float* W2   = (const float*)d_in[6];
    const float* b2   = (const float*)d_in[7];
    const float* Wlin = (const float*)d_in[8];
    const float* blin = (const float*)d_in[9];
    float* out = (float*)d_out;

    k_zero<<<512, 256>>>();
    k_count<<<2048, 256>>>(edst);
    k_dinv<<<(N_NODES + 255) / 256, 256>>>();
    k_scan<<<1, 1024>>>();
    k_fill<<<2048, 256>>>(esrc, edst);
    k_agg1<<<(N_NODES + 127) / 128, 128>>>(x);
    k_gemm1<<<N_NODES, HID>>>(W1, b1);
    k_agg2<<<N_NODES, HID>>>();
    k_gemm2pool<<<N_NODES, HID>>>(W2, b2, batch);
    k_final<<<NUM_GRAPHS, 32>>>(Wlin, blin, out);
}

// round 3
// speedup vs baseline: 1.9359x; 1.9359x over previous
#include <cuda_runtime.h>
#include <cuda_bf16.h>

#define N_NODES 100000
#define N_EDGES 1600000
#define NUM_GRAPHS 4096
#define HID 128
#define F_IN 11
#define F_OUT 19

#define SCAN_CHUNK 2048
#define SCAN_NBLK ((N_NODES + SCAN_CHUNK - 1) / SCAN_CHUNK)   // 49

// ---------------- scratch (static device globals; no allocation) ----------------
__device__ int   g_cnt[N_NODES];
__device__ int   g_fill[N_NODES];
__device__ float g_dinv[N_NODES];
__device__ int   g_rowptr[N_NODES + 1];
__device__ int   g_csr_src[N_EDGES];
__device__ float g_csr_norm[N_EDGES];
__device__ float g_agg1[N_NODES * F_IN];
__device__ float g_h1[N_NODES * HID];
__device__ float g_agg2[N_NODES * HID];
__device__ float g_sums[NUM_GRAPHS * HID];
__device__ float g_gcnt[NUM_GRAPHS];
__device__ int   g_bsum[64];
__device__ int   g_boff[64];

// ---------------- helpers ----------------
typedef unsigned long long ull;

__device__ __forceinline__ ull fma2(ull a, ull b, ull c) {
    ull d;
    asm("fma.rn.f32x2 %0, %1, %2, %3;" : "=l"(d) : "l"(a), "l"(b), "l"(c));
    return d;
}
__device__ __forceinline__ ull pack2(float lo, float hi) {
    ull d;
    asm("mov.b64 %0, {%1, %2};" : "=l"(d) : "f"(lo), "f"(hi));
    return d;
}
__device__ __forceinline__ void unpack2(ull v, float& lo, float& hi) {
    asm("mov.b64 {%0, %1}, %2;" : "=f"(lo), "=f"(hi) : "l"(v));
}

// ---------------- kernels ----------------

__global__ void k_zero() {
    int i = blockIdx.x * blockDim.x + threadIdx.x;
    int stride = gridDim.x * blockDim.x;
    for (int j = i; j < N_NODES; j += stride) { g_cnt[j] = 0; g_fill[j] = 0; }
    for (int j = i; j < NUM_GRAPHS * HID; j += stride) g_sums[j] = 0.f;
    for (int j = i; j < NUM_GRAPHS; j += stride) g_gcnt[j] = 0.f;
}

__global__ void k_count(const int* __restrict__ dst) {
    int i = blockIdx.x * blockDim.x + threadIdx.x;
    int stride = gridDim.x * blockDim.x;
    for (int e = i; e < N_EDGES; e += stride)
        atomicAdd(&g_cnt[dst[e]], 1);
}

__global__ void k_dinv() {
    int i = blockIdx.x * blockDim.x + threadIdx.x;
    if (i < N_NODES)
        g_dinv[i] = rsqrtf((float)(g_cnt[i] + 1));
}

// ---- 3-phase scan ----
__global__ void k_scan1() {
    __shared__ int sm[1024];
    int t = threadIdx.x;
    int base = blockIdx.x * SCAN_CHUNK;
    int i0 = base + 2 * t, i1 = i0 + 1;
    int v0 = (i0 < N_NODES) ? g_cnt[i0] : 0;
    int v1 = (i1 < N_NODES) ? g_cnt[i1] : 0;
    int s = v0 + v1;
    sm[t] = s;
    __syncthreads();
    for (int off = 1; off < 1024; off <<= 1) {
        int add = (t >= off) ? sm[t - off] : 0;
        __syncthreads();
        sm[t] += add;
        __syncthreads();
    }
    int excl = sm[t] - s;
    if (i0 < N_NODES) g_rowptr[i0] = excl;
    if (i1 < N_NODES) g_rowptr[i1] = excl + v0;
    if (t == 1023) g_bsum[blockIdx.x] = sm[t];
}

__global__ void k_scan2() {
    __shared__ int sm[64];
    int t = threadIdx.x;   // 64
    int v = (t < SCAN_NBLK) ? g_bsum[t] : 0;
    sm[t] = v;
    __syncthreads();
    for (int off = 1; off < 64; off <<= 1) {
        int add = (t >= off) ? sm[t - off] : 0;
        __syncthreads();
        sm[t] += add;
        __syncthreads();
    }
    g_boff[t] = sm[t] - v;   // exclusive
}

__global__ void k_scan3() {
    int i = blockIdx.x * blockDim.x + threadIdx.x;
    if (i < N_NODES) g_rowptr[i] += g_boff[i >> 11];
    if (i == 0) g_rowptr[N_NODES] = N_EDGES;
}

__global__ void k_fill(const int* __restrict__ src, const int* __restrict__ dst) {
    int i = blockIdx.x * blockDim.x + threadIdx.x;
    int stride = gridDim.x * blockDim.x;
    for (int e = i; e < N_EDGES; e += stride) {
        int s = src[e], d = dst[e];
        int pos = g_rowptr[d] + atomicAdd(&g_fill[d], 1);
        g_csr_src[pos] = s;
        g_csr_norm[pos] = g_dinv[s] * g_dinv[d];
    }
}

// layer-1 aggregation on RAW inputs (11 features)
__global__ void k_agg1(const float* __restrict__ x) {
    int i = blockIdx.x * blockDim.x + threadIdx.x;
    if (i >= N_NODES) return;
    float di = g_dinv[i];
    float selfw = di * di;
    float acc[F_IN];
#pragma unroll
    for (int f = 0; f < F_IN; f++) acc[f] = x[i * F_IN + f] * selfw;
    int rs = g_rowptr[i], re = g_rowptr[i + 1];
    for (int e = rs; e < re; e++) {
        int s = g_csr_src[e];
        float w = g_csr_norm[e];
#pragma unroll
        for (int f = 0; f < F_IN; f++) acc[f] += x[s * F_IN + f] * w;
    }
#pragma unroll
    for (int f = 0; f < F_IN; f++) g_agg1[i * F_IN + f] = acc[f];
}

// h1 = relu(agg1 @ W1 + b1)
__global__ void k_gemm1(const float* __restrict__ W1, const float* __restrict__ b1) {
    int i = blockIdx.x;
    int f = threadIdx.x;
    __shared__ float sa[F_IN];
    if (f < F_IN) sa[f] = g_agg1[i * F_IN + f];
    __syncthreads();
    float acc = b1[f];
#pragma unroll
    for (int k = 0; k < F_IN; k++) acc = fmaf(sa[k], W1[k * HID + f], acc);
    g_h1[i * HID + f] = fmaxf(acc, 0.f);
}

// layer-2 aggregation of h1 (128-wide). One block (128 threads) per node.
__global__ void k_agg2() {
    int i = blockIdx.x;
    int f = threadIdx.x;
    float di = g_dinv[i];
    float acc = g_h1[i * HID + f] * di * di;
    int rs = g_rowptr[i], re = g_rowptr[i + 1];
    for (int e = rs; e < re; e++) {
        int s = g_csr_src[e];
        float w = g_csr_norm[e];
        acc = fmaf(g_h1[s * HID + f], w, acc);
    }
    g_agg2[i * HID + f] = acc;
}

// ---- tiled GEMM2 + fused mean-pool (f32x2 packed FMA) ----
// tile: 64 nodes x 128 outputs, 256 threads; thread: 8 nodes (4 pairs) x 4 outputs
#define TM 64
#define TKK 16
__global__ void __launch_bounds__(256) k_gemm2pool(const float* __restrict__ W2,
                                                   const float* __restrict__ b2,
                                                   const int* __restrict__ batch) {
    __shared__ float As[TKK][TM + 4];   // +4 pad (keeps 16B align, breaks bank conflict)
    __shared__ float Ws[TKK][HID];
    int tid = threadIdx.x;
    int node0 = blockIdx.x * TM;
    int tn = (tid >> 5) * 8;     // 0..56, node offset within tile
    int tf = (tid & 31) * 4;     // 0..124, output offset

    ull acc[4][4];
#pragma unroll
    for (int i = 0; i < 4; i++)
#pragma unroll
        for (int j = 0; j < 4; j++) acc[i][j] = 0ull;

    for (int k0 = 0; k0 < HID; k0 += TKK) {
        // load A tile: 64 nodes x 16 k  (1024 elems, 4/thread)
#pragma unroll
        for (int p = 0; p < 4; p++) {
            int idx = tid + p * 256;
            int kk = idx & 15, nn = idx >> 4;
            int node = node0 + nn;
            As[kk][nn] = (node < N_NODES) ? g_agg2[node * HID + k0 + kk] : 0.f;
        }
        // load W tile: 16 x 128 (2048 elems, 8/thread)
#pragma unroll
        for (int p = 0; p < 8; p++) {
            int idx = tid + p * 256;
            int kk = idx >> 7, ff = idx & 127;
            Ws[kk][ff] = W2[(k0 + kk) * HID + ff];
        }
        __syncthreads();
#pragma unroll
        for (int k = 0; k < TKK; k++) {
            ull a0 = *(const ull*)&As[k][tn];
            ull a1 = *(const ull*)&As[k][tn + 2];
            ull a2 = *(const ull*)&As[k][tn + 4];
            ull a3 = *(const ull*)&As[k][tn + 6];
            float4 w = *(const float4*)&Ws[k][tf];
            ull w0 = pack2(w.x, w.x);
            ull w1 = pack2(w.y, w.y);
            ull w2 = pack2(w.z, w.z);
            ull w3 = pack2(w.w, w.w);
            acc[0][0] = fma2(a0, w0, acc[0][0]);
            acc[0][1] = fma2(a0, w1, acc[0][1]);
            acc[0][2] = fma2(a0, w2, acc[0][2]);
            acc[0][3] = fma2(a0, w3, acc[0][3]);
            acc[1][0] = fma2(a1, w0, acc[1][0]);
            acc[1][1] = fma2(a1, w1, acc[1][1]);
            acc[1][2] = fma2(a1, w2, acc[1][2]);
            acc[1][3] = fma2(a1, w3, acc[1][3]);
            acc[2][0] = fma2(a2, w0, acc[2][0]);
            acc[2][1] = fma2(a2, w1, acc[2][1]);
            acc[2][2] = fma2(a2, w2, acc[2][2]);
            acc[2][3] = fma2(a2, w3, acc[2][3]);
            acc[3][0] = fma2(a3, w0, acc[3][0]);
            acc[3][1] = fma2(a3, w1, acc[3][1]);
            acc[3][2] = fma2(a3, w2, acc[3][2]);
            acc[3][3] = fma2(a3, w3, acc[3][3]);
        }
        __syncthreads();
    }

    // epilogue: unpack, add bias, run-length merge by (sorted) batch id, atomic once per run
    float4 bb = *(const float4*)&b2[tf];
    float out[8][4];
#pragma unroll
    for (int p = 0; p < 4; p++) {
#pragma unroll
        for (int j = 0; j < 4; j++) {
            float lo, hi;
            unpack2(acc[p][j], lo, hi);
            out[2 * p][j] = lo;
            out[2 * p + 1][j] = hi;
        }
        out[2 * p][0] += bb.x;  out[2 * p][1] += bb.y;  out[2 * p][2] += bb.z;  out[2 * p][3] += bb.w;
        out[2 * p + 1][0] += bb.x; out[2 * p + 1][1] += bb.y; out[2 * p + 1][2] += bb.z; out[2 * p + 1][3] += bb.w;
    }

    int nvalid = N_NODES - node0;   // may exceed 8; clamp below
    int gprev = -1;
    float run0 = 0.f, run1 = 0.f, run2 = 0.f, run3 = 0.f;
    float runc = 0.f;
#pragma unroll
    for (int i = 0; i < 8; i++) {
        int node = node0 + tn + i;
        if (tn + i >= nvalid) break;
        int g = batch[node];
        if (g != gprev) {
            if (gprev >= 0) {
                atomicAdd(&g_sums[gprev * HID + tf + 0], run0);
                atomicAdd(&g_sums[gprev * HID + tf + 1], run1);
                atomicAdd(&g_sums[gprev * HID + tf + 2], run2);
                atomicAdd(&g_sums[gprev * HID + tf + 3], run3);
                if (tf == 0) atomicAdd(&g_gcnt[gprev], runc);
            }
            gprev = g; run0 = run1 = run2 = run3 = 0.f; runc = 0.f;
        }
        run0 += out[i][0]; run1 += out[i][1]; run2 += out[i][2]; run3 += out[i][3];
        runc += 1.f;
    }
    if (gprev >= 0) {
        atomicAdd(&g_sums[gprev * HID + tf + 0], run0);
        atomicAdd(&g_sums[gprev * HID + tf + 1], run1);
        atomicAdd(&g_sums[gprev * HID + tf + 2], run2);
        atomicAdd(&g_sums[gprev * HID + tf + 3], run3);
        if (tf == 0) atomicAdd(&g_gcnt[gprev], runc);
    }
}

// out = (sums / max(cnt,1)) @ Wlin + blin
__global__ void k_final(const float* __restrict__ Wlin, const float* __restrict__ blin,
                        float* __restrict__ out) {
    int g = blockIdx.x;
    int o = threadIdx.x;
    __shared__ float sp[HID];
    for (int k = o; k < HID; k += 32) sp[k] = g_sums[g * HID + k];
    __syncthreads();
    float inv = 1.f / fmaxf(g_gcnt[g], 1.f);
    if (o < F_OUT) {
        float acc = blin[o];
#pragma unroll 8
        for (int k = 0; k < HID; k++) acc = fmaf(sp[k] * inv, Wlin[k * F_OUT + o], acc);
        out[g * F_OUT + o] = acc;
    }
}

// ---------------- launch ----------------
extern "C" void kernel_launch(void* const* d_in, const int* in_sizes, int n_in,
                              void* d_out, int out_size) {
    const float* x    = (const float*)d_in[0];
    const int*   esrc = (const int*)d_in[1];
    const int*   edst = (const int*)d_in[2];
    const int*   batch= (const int*)d_in[3];
    const float* W1   = (const float*)d_in[4];
    const float* b1   = (const float*)d_in[5];
    const float* W2   = (const float*)d_in[6];
    const float* b2   = (const float*)d_in[7];
    const float* Wlin = (const float*)d_in[8];
    const float* blin = (const float*)d_in[9];
    float* out = (float*)d_out;

    k_zero<<<512, 256>>>();
    k_count<<<2048, 256>>>(edst);
    k_dinv<<<(N_NODES + 255) / 256, 256>>>();
    k_scan1<<<SCAN_NBLK, 1024>>>();
    k_scan2<<<1, 64>>>();
    k_scan3<<<(N_NODES + 255) / 256, 256>>>();
    k_fill<<<2048, 256>>>(esrc, edst);
    k_agg1<<<(N_NODES + 127) / 128, 128>>>(x);
    k_gemm1<<<N_NODES, HID>>>(W1, b1);
    k_agg2<<<N_NODES, HID>>>();
    k_gemm2pool<<<(N_NODES + TM - 1) / TM, 256>>>(W2, b2, batch);
    k_final<<<NUM_GRAPHS, 32>>>(Wlin, blin, out);
}

// round 5
// speedup vs baseline: 2.0264x; 1.0468x over previous
#include <cuda_runtime.h>
#include <cuda_fp16.h>

#define N_NODES 100000
#define N_EDGES 1600000
#define NUM_GRAPHS 4096
#define HID 128
#define F_IN 11
#define F_OUT 19

#define SCAN_CHUNK 2048
#define SCAN_NBLK ((N_NODES + SCAN_CHUNK - 1) / SCAN_CHUNK)   // 49
#define TM 64

// ---------------- scratch (static device globals; no allocation) ----------------
__device__ int    g_cnt[N_NODES];
__device__ int    g_fill[N_NODES];
__device__ float  g_dinv[N_NODES];
__device__ int    g_rowptr[N_NODES + 1];
__device__ int2   g_csr2[N_EDGES];            // {src, norm as float bits}
__device__ float  g_agg1[N_NODES * F_IN];
__device__ __half g_h1h[N_NODES * HID];       // fp16 h1
__device__ float  g_sums[NUM_GRAPHS * HID];
__device__ float  g_gcnt[NUM_GRAPHS];
__device__ int    g_bsum[64];
__device__ int    g_boff[64];

// ---------------- helpers ----------------
typedef unsigned long long ull;

__device__ __forceinline__ ull fma2(ull a, ull b, ull c) {
    ull d;
    asm("fma.rn.f32x2 %0, %1, %2, %3;" : "=l"(d) : "l"(a), "l"(b), "l"(c));
    return d;
}
__device__ __forceinline__ ull pack2(float lo, float hi) {
    ull d;
    asm("mov.b64 %0, {%1, %2};" : "=l"(d) : "f"(lo), "f"(hi));
    return d;
}
__device__ __forceinline__ void unpack2(ull v, float& lo, float& hi) {
    asm("mov.b64 {%0, %1}, %2;" : "=f"(lo), "=f"(hi) : "l"(v));
}

// ---------------- kernels ----------------

__global__ void k_zero() {
    int i = blockIdx.x * blockDim.x + threadIdx.x;
    int stride = gridDim.x * blockDim.x;
    for (int j = i; j < N_NODES; j += stride) { g_cnt[j] = 0; g_fill[j] = 0; }
    for (int j = i; j < NUM_GRAPHS * HID; j += stride) g_sums[j] = 0.f;
    for (int j = i; j < NUM_GRAPHS; j += stride) g_gcnt[j] = 0.f;
}

__global__ void k_count(const int* __restrict__ dst) {
    int i = blockIdx.x * blockDim.x + threadIdx.x;
    int stride = gridDim.x * blockDim.x;
    for (int e = i; e < N_EDGES; e += stride)
        atomicAdd(&g_cnt[dst[e]], 1);
}

// ---- 3-phase scan (+ dinv fused into phase 1) ----
__global__ void k_scan1() {
    __shared__ int sm[1024];
    int t = threadIdx.x;
    int base = blockIdx.x * SCAN_CHUNK;
    int i0 = base + 2 * t, i1 = i0 + 1;
    int v0 = (i0 < N_NODES) ? g_cnt[i0] : 0;
    int v1 = (i1 < N_NODES) ? g_cnt[i1] : 0;
    if (i0 < N_NODES) g_dinv[i0] = rsqrtf((float)(v0 + 1));
    if (i1 < N_NODES) g_dinv[i1] = rsqrtf((float)(v1 + 1));
    int s = v0 + v1;
    sm[t] = s;
    __syncthreads();
    for (int off = 1; off < 1024; off <<= 1) {
        int add = (t >= off) ? sm[t - off] : 0;
        __syncthreads();
        sm[t] += add;
        __syncthreads();
    }
    int excl = sm[t] - s;
    if (i0 < N_NODES) g_rowptr[i0] = excl;
    if (i1 < N_NODES) g_rowptr[i1] = excl + v0;
    if (t == 1023) g_bsum[blockIdx.x] = sm[t];
}

__global__ void k_scan2() {
    __shared__ int sm[64];
    int t = threadIdx.x;
    int v = (t < SCAN_NBLK) ? g_bsum[t] : 0;
    sm[t] = v;
    __syncthreads();
    for (int off = 1; off < 64; off <<= 1) {
        int add = (t >= off) ? sm[t - off] : 0;
        __syncthreads();
        sm[t] += add;
        __syncthreads();
    }
    g_boff[t] = sm[t] - v;
}

__global__ void k_scan3() {
    int i = blockIdx.x * blockDim.x + threadIdx.x;
    if (i < N_NODES) g_rowptr[i] += g_boff[i >> 11];
    if (i == 0) g_rowptr[N_NODES] = N_EDGES;
}

__global__ void k_fill(const int* __restrict__ src, const int* __restrict__ dst) {
    int i = blockIdx.x * blockDim.x + threadIdx.x;
    int stride = gridDim.x * blockDim.x;
    for (int e = i; e < N_EDGES; e += stride) {
        int s = src[e], d = dst[e];
        int pos = g_rowptr[d] + atomicAdd(&g_fill[d], 1);
        g_csr2[pos] = make_int2(s, __float_as_int(g_dinv[s] * g_dinv[d]));
    }
}

// layer-1 aggregation on RAW inputs (11 features), thread-per-node
__global__ void k_agg1(const float* __restrict__ x) {
    int i = blockIdx.x * blockDim.x + threadIdx.x;
    if (i >= N_NODES) return;
    float di = g_dinv[i];
    float selfw = di * di;
    float acc[F_IN];
#pragma unroll
    for (int f = 0; f < F_IN; f++) acc[f] = x[i * F_IN + f] * selfw;
    int rs = g_rowptr[i], re = g_rowptr[i + 1];
    for (int e = rs; e < re; e++) {
        int2 cw = g_csr2[e];
        int s = cw.x;
        float w = __int_as_float(cw.y);
#pragma unroll
        for (int f = 0; f < F_IN; f++) acc[f] += x[s * F_IN + f] * w;
    }
#pragma unroll
    for (int f = 0; f < F_IN; f++) g_agg1[i * F_IN + f] = acc[f];
}

// h1 = relu(agg1 @ W1 + b1), stored fp16
__global__ void k_gemm1(const float* __restrict__ W1, const float* __restrict__ b1) {
    int i = blockIdx.x;
    int f = threadIdx.x;
    __shared__ float sa[F_IN];
    if (f < F_IN) sa[f] = g_agg1[i * F_IN + f];
    __syncthreads();
    float acc = b1[f];
#pragma unroll
    for (int k = 0; k < F_IN; k++) acc = fmaf(sa[k], W1[k * HID + f], acc);
    g_h1h[i * HID + f] = __float2half_rn(fmaxf(acc, 0.f));
}

// ---- fused: layer-2 aggregation (into smem) + GEMM2 + mean-pool ----
// block = 256 threads (8 warps), tile = 64 nodes x 128 outputs
__global__ void __launch_bounds__(256) k_fused(const float* __restrict__ W2,
                                               const float* __restrict__ b2,
                                               const int* __restrict__ batch) {
    __shared__ float As[TM][HID + 4];   // node-major aggregated tile
    __shared__ float Ws[16][HID];
    int tid = threadIdx.x;
    int wi = tid >> 5, l = tid & 31;
    int node0 = blockIdx.x * TM;

    // ---- phase A: each warp aggregates 8 nodes; lane owns 4 features ----
    for (int i = 0; i < 8; i++) {
        int nn = wi * 8 + i;
        int node = node0 + nn;
        float a0 = 0.f, a1 = 0.f, a2 = 0.f, a3 = 0.f;
        if (node < N_NODES) {
            float di = g_dinv[node];
            float selfw = di * di;
            uint2 hu = *(const uint2*)&g_h1h[node * HID + l * 4];
            float2 s01 = __half22float2(*(__half2*)&hu.x);
            float2 s23 = __half22float2(*(__half2*)&hu.y);
            a0 = s01.x * selfw; a1 = s01.y * selfw;
            a2 = s23.x * selfw; a3 = s23.y * selfw;
            int rs = g_rowptr[node], re = g_rowptr[node + 1];
            for (int e0 = rs; e0 < re; e0 += 32) {
                int cnt = min(32, re - e0);
                int2 cw = make_int2(0, 0);
                if (e0 + l < re) cw = g_csr2[e0 + l];
#pragma unroll 4
                for (int j = 0; j < cnt; j++) {
                    int s = __shfl_sync(0xffffffffu, cw.x, j);
                    float wg = __int_as_float(__shfl_sync(0xffffffffu, cw.y, j));
                    uint2 hv = *(const uint2*)&g_h1h[s * HID + l * 4];
                    float2 h01 = __half22float2(*(__half2*)&hv.x);
                    float2 h23 = __half22float2(*(__half2*)&hv.y);
                    a0 = fmaf(h01.x, wg, a0);
                    a1 = fmaf(h01.y, wg, a1);
                    a2 = fmaf(h23.x, wg, a2);
                    a3 = fmaf(h23.y, wg, a3);
                }
            }
        }
        *(float4*)&As[nn][l * 4] = make_float4(a0, a1, a2, a3);
    }
    __syncthreads();

    // ---- phase B: tiled GEMM from smem, f32x2 packed over output pairs ----
    int tn = wi * 8;
    int tf = l * 4;
    ull acc[8][2];
#pragma unroll
    for (int i = 0; i < 8; i++) { acc[i][0] = 0ull; acc[i][1] = 0ull; }

    for (int k0 = 0; k0 < HID; k0 += 16) {
        // stage Ws: 16x128 floats = 512 float4, 2 per thread
#pragma unroll
        for (int p = 0; p < 2; p++) {
            int idx = tid + p * 256;
            int kk = idx >> 5;
            int ff = (idx << 2) & 127;
            *(float4*)&Ws[kk][ff] = *(const float4*)&W2[(k0 + kk) * HID + ff];
        }
        __syncthreads();
#pragma unroll
        for (int k = 0; k < 16; k++) {
            ull w01 = *(const ull*)&Ws[k][tf];
            ull w23 = *(const ull*)&Ws[k][tf + 2];
#pragma unroll
            for (int i = 0; i < 8; i++) {
                float a = As[tn + i][k0 + k];
                ull aa = pack2(a, a);
                acc[i][0] = fma2(aa, w01, acc[i][0]);
                acc[i][1] = fma2(aa, w23, acc[i][1]);
            }
        }
        __syncthreads();
    }

    // ---- epilogue: bias + run-length merge by sorted batch id, then atomics ----
    float4 bb = *(const float4*)&b2[tf];
    float outv[8][4];
#pragma unroll
    for (int i = 0; i < 8; i++) {
        unpack2(acc[i][0], outv[i][0], outv[i][1]);
        unpack2(acc[i][1], outv[i][2], outv[i][3]);
        outv[i][0] += bb.x; outv[i][1] += bb.y;
        outv[i][2] += bb.z; outv[i][3] += bb.w;
    }

    int nvalid = N_NODES - node0;
    int gprev = -1;
    float run0 = 0.f, run1 = 0.f, run2 = 0.f, run3 = 0.f, runc = 0.f;
#pragma unroll
    for (int i = 0; i < 8; i++) {
        if (tn + i >= nvalid) break;
        int node = node0 + tn + i;
        int g = batch[node];
        if (g != gprev) {
            if (gprev >= 0) {
                atomicAdd(&g_sums[gprev * HID + tf + 0], run0);
                atomicAdd(&g_sums[gprev * HID + tf + 1], run1);
                atomicAdd(&g_sums[gprev * HID + tf + 2], run2);
                atomicAdd(&g_sums[gprev * HID + tf + 3], run3);
                if (tf == 0) atomicAdd(&g_gcnt[gprev], runc);
            }
            gprev = g; run0 = run1 = run2 = run3 = 0.f; runc = 0.f;
        }
        run0 += outv[i][0]; run1 += outv[i][1];
        run2 += outv[i][2]; run3 += outv[i][3];
        runc += 1.f;
    }
    if (gprev >= 0) {
        atomicAdd(&g_sums[gprev * HID + tf + 0], run0);
        atomicAdd(&g_sums[gprev * HID + tf + 1], run1);
        atomicAdd(&g_sums[gprev * HID + tf + 2], run2);
        atomicAdd(&g_sums[gprev * HID + tf + 3], run3);
        if (tf == 0) atomicAdd(&g_gcnt[gprev], runc);
    }
}

// out = (sums / max(cnt,1)) @ Wlin + blin
__global__ void k_final(const float* __restrict__ Wlin, const float* __restrict__ blin,
                        float* __restrict__ out) {
    int g = blockIdx.x;
    int o = threadIdx.x;
    __shared__ float sp[HID];
    for (int k = o; k < HID; k += 32) sp[k] = g_sums[g * HID + k];
    __syncthreads();
    float inv = 1.f / fmaxf(g_gcnt[g], 1.f);
    if (o < F_OUT) {
        float acc = blin[o];
#pragma unroll 8
        for (int k = 0; k < HID; k++) acc = fmaf(sp[k] * inv, Wlin[k * F_OUT + o], acc);
        out[g * F_OUT + o] = acc;
    }
}

// ---------------- launch ----------------
extern "C" void kernel_launch(void* const* d_in, const int* in_sizes, int n_in,
                              void* d_out, int out_size) {
    const float* x    = (const float*)d_in[0];
    const int*   esrc = (const int*)d_in[1];
    const int*   edst = (const int*)d_in[2];
    const int*   batch= (const int*)d_in[3];
    const float* W1   = (const float*)d_in[4];
    const float* b1   = (const float*)d_in[5];
    const float* W2   = (const float*)d_in[6];
    const float* b2   = (const float*)d_in[7];
    const float* Wlin = (const float*)d_in[8];
    const float* blin = (const float*)d_in[9];
    float* out = (float*)d_out;

    k_zero<<<512, 256>>>();
    k_count<<<2048, 256>>>(edst);
    k_scan1<<<SCAN_NBLK, 1024>>>();
    k_scan2<<<1, 64>>>();
    k_scan3<<<(N_NODES + 255) / 256, 256>>>();
    k_fill<<<2048, 256>>>(esrc, edst);
    k_agg1<<<(N_NODES + 127) / 128, 128>>>(x);
    k_gemm1<<<N_NODES, HID>>>(W1, b1);
    k_fused<<<(N_NODES + TM - 1) / TM, 256>>>(W2, b2, batch);
    k_final<<<NUM_GRAPHS, 32>>>(Wlin, blin, out);
}

// round 6
// speedup vs baseline: 4.2856x; 2.1149x over previous
#include <cuda_runtime.h>
#include <cuda_fp16.h>

#define N_NODES 100000
#define N_EDGES 1600000
#define NUM_GRAPHS 4096
#define HID 128
#define F_IN 11
#define F_PAD 12
#define F_OUT 19

#define SCAN_CHUNK 2048
#define SCAN_NBLK ((N_NODES + SCAN_CHUNK - 1) / SCAN_CHUNK)   // 49

// ---------------- scratch (static device globals; no allocation) ----------------
__device__ int    g_cnt[N_NODES];
__device__ int    g_fill[N_NODES];
__device__ float  g_dinv[N_NODES];
__device__ int    g_rowptr[N_NODES + 1];
__device__ int2   g_csr2[N_EDGES];            // {src, norm as float bits}
__device__ float  g_x12[N_NODES * F_PAD];     // x padded to 12 floats/row
__device__ float  g_agg1[N_NODES * F_PAD];    // layer-1 aggregated (padded)
__device__ __half g_h1h[N_NODES * HID];       // fp16 h1
__device__ float  g_q[NUM_GRAPHS * HID];      // pooled aggregated features
__device__ float  g_gcnt[NUM_GRAPHS];
__device__ float  g_Wc[HID * F_OUT];          // W2 @ Wlin
__device__ float  g_bc[F_OUT];                // b2 @ Wlin + blin
__device__ int    g_bsum[64];
__device__ int    g_boff[64];

// ---------------- kernels ----------------

__global__ void k_zero() {
    int i = blockIdx.x * blockDim.x + threadIdx.x;
    int stride = gridDim.x * blockDim.x;
    for (int j = i; j < N_NODES; j += stride) { g_cnt[j] = 0; g_fill[j] = 0; }
    for (int j = i; j < NUM_GRAPHS * HID; j += stride) g_q[j] = 0.f;
    for (int j = i; j < NUM_GRAPHS; j += stride) g_gcnt[j] = 0.f;
}

// edge in-degree count + per-graph node count
__global__ void k_count(const int* __restrict__ dst, const int* __restrict__ batch) {
    int i = blockIdx.x * blockDim.x + threadIdx.x;
    int stride = gridDim.x * blockDim.x;
    for (int e = i; e < N_EDGES; e += stride)
        atomicAdd(&g_cnt[dst[e]], 1);
    for (int n = i; n < N_NODES; n += stride)
        atomicAdd(&g_gcnt[batch[n]], 1.f);
}

// ---- 3-phase scan (+ dinv fused into phase 1) ----
__global__ void k_scan1() {
    __shared__ int sm[1024];
    int t = threadIdx.x;
    int base = blockIdx.x * SCAN_CHUNK;
    int i0 = base + 2 * t, i1 = i0 + 1;
    int v0 = (i0 < N_NODES) ? g_cnt[i0] : 0;
    int v1 = (i1 < N_NODES) ? g_cnt[i1] : 0;
    if (i0 < N_NODES) g_dinv[i0] = rsqrtf((float)(v0 + 1));
    if (i1 < N_NODES) g_dinv[i1] = rsqrtf((float)(v1 + 1));
    int s = v0 + v1;
    sm[t] = s;
    __syncthreads();
    for (int off = 1; off < 1024; off <<= 1) {
        int add = (t >= off) ? sm[t - off] : 0;
        __syncthreads();
        sm[t] += add;
        __syncthreads();
    }
    int excl = sm[t] - s;
    if (i0 < N_NODES) g_rowptr[i0] = excl;
    if (i1 < N_NODES) g_rowptr[i1] = excl + v0;
    if (t == 1023) g_bsum[blockIdx.x] = sm[t];
}

__global__ void k_scan2() {
    __shared__ int sm[64];
    int t = threadIdx.x;
    int v = (t < SCAN_NBLK) ? g_bsum[t] : 0;
    sm[t] = v;
    __syncthreads();
    for (int off = 1; off < 64; off <<= 1) {
        int add = (t >= off) ? sm[t - off] : 0;
        __syncthreads();
        sm[t] += add;
        __syncthreads();
    }
    g_boff[t] = sm[t] - v;
}

__global__ void k_scan3() {
    int i = blockIdx.x * blockDim.x + threadIdx.x;
    if (i < N_NODES) g_rowptr[i] += g_boff[i >> 11];
    if (i == 0) g_rowptr[N_NODES] = N_EDGES;
}

__global__ void k_fill(const int* __restrict__ src, const int* __restrict__ dst) {
    int i = blockIdx.x * blockDim.x + threadIdx.x;
    int stride = gridDim.x * blockDim.x;
    for (int e = i; e < N_EDGES; e += stride) {
        int s = src[e], d = dst[e];
        int pos = g_rowptr[d] + atomicAdd(&g_fill[d], 1);
        g_csr2[pos] = make_int2(s, __float_as_int(g_dinv[s] * g_dinv[d]));
    }
}

// pad x rows from 11 to 12 floats (enables float4 gathers)
__global__ void k_padx(const float* __restrict__ x) {
    int idx = blockIdx.x * blockDim.x + threadIdx.x;
    int stride = gridDim.x * blockDim.x;
    for (int j = idx; j < N_NODES * F_PAD; j += stride) {
        int i = j / F_PAD, f = j - i * F_PAD;
        g_x12[j] = (f < F_IN) ? x[i * F_IN + f] : 0.f;
    }
}

// layer-1 aggregation on padded inputs, thread-per-node, float4 gathers
__global__ void k_agg1() {
    int i = blockIdx.x * blockDim.x + threadIdx.x;
    if (i >= N_NODES) return;
    float di = g_dinv[i];
    float selfw = di * di;
    float4 a0 = *(const float4*)&g_x12[i * F_PAD];
    float4 a1 = *(const float4*)&g_x12[i * F_PAD + 4];
    float4 a2 = *(const float4*)&g_x12[i * F_PAD + 8];
    a0.x *= selfw; a0.y *= selfw; a0.z *= selfw; a0.w *= selfw;
    a1.x *= selfw; a1.y *= selfw; a1.z *= selfw; a1.w *= selfw;
    a2.x *= selfw; a2.y *= selfw; a2.z *= selfw; a2.w *= selfw;
    int rs = g_rowptr[i], re = g_rowptr[i + 1];
#pragma unroll 2
    for (int e = rs; e < re; e++) {
        int2 cw = g_csr2[e];
        int s = cw.x;
        float w = __int_as_float(cw.y);
        float4 x0 = *(const float4*)&g_x12[s * F_PAD];
        float4 x1 = *(const float4*)&g_x12[s * F_PAD + 4];
        float4 x2 = *(const float4*)&g_x12[s * F_PAD + 8];
        a0.x = fmaf(x0.x, w, a0.x); a0.y = fmaf(x0.y, w, a0.y);
        a0.z = fmaf(x0.z, w, a0.z); a0.w = fmaf(x0.w, w, a0.w);
        a1.x = fmaf(x1.x, w, a1.x); a1.y = fmaf(x1.y, w, a1.y);
        a1.z = fmaf(x1.z, w, a1.z); a1.w = fmaf(x1.w, w, a1.w);
        a2.x = fmaf(x2.x, w, a2.x); a2.y = fmaf(x2.y, w, a2.y);
        a2.z = fmaf(x2.z, w, a2.z); a2.w = fmaf(x2.w, w, a2.w);
    }
    *(float4*)&g_agg1[i * F_PAD]     = a0;
    *(float4*)&g_agg1[i * F_PAD + 4] = a1;
    *(float4*)&g_agg1[i * F_PAD + 8] = a2;
}

// h1 = relu(agg1 @ W1 + b1) -> fp16 ; warp-per-node, W1 staged in smem
__global__ void __launch_bounds__(256) k_gemm1(const float* __restrict__ W1,
                                               const float* __restrict__ b1) {
    __shared__ float sw[F_IN][HID];
    __shared__ float sb[HID];
    int tid = threadIdx.x;
    for (int i = tid; i < F_IN * HID; i += 256) sw[i / HID][i % HID] = W1[i];
    for (int i = tid; i < HID; i += 256) sb[i] = b1[i];
    __syncthreads();
    int wi = tid >> 5, l = tid & 31;
    int f = l * 4;
    for (int node = blockIdx.x * 8 + wi; node < N_NODES; node += gridDim.x * 8) {
        float4 x0 = *(const float4*)&g_agg1[node * F_PAD];
        float4 x1 = *(const float4*)&g_agg1[node * F_PAD + 4];
        float4 x2 = *(const float4*)&g_agg1[node * F_PAD + 8];
        float xr[F_IN] = {x0.x, x0.y, x0.z, x0.w, x1.x, x1.y, x1.z, x1.w, x2.x, x2.y, x2.z};
        float4 acc = *(const float4*)&sb[f];
#pragma unroll
        for (int k = 0; k < F_IN; k++) {
            float4 w = *(const float4*)&sw[k][f];
            acc.x = fmaf(xr[k], w.x, acc.x);
            acc.y = fmaf(xr[k], w.y, acc.y);
            acc.z = fmaf(xr[k], w.z, acc.z);
            acc.w = fmaf(xr[k], w.w, acc.w);
        }
        uint2 st;
        *(__half2*)&st.x = __floats2half2_rn(fmaxf(acc.x, 0.f), fmaxf(acc.y, 0.f));
        *(__half2*)&st.y = __floats2half2_rn(fmaxf(acc.z, 0.f), fmaxf(acc.w, 0.f));
        *(uint2*)&g_h1h[node * HID + f] = st;
    }
}

// Wc = W2 @ Wlin, bc = b2 @ Wlin + blin
__global__ void k_wc(const float* __restrict__ W2, const float* __restrict__ b2,
                     const float* __restrict__ Wlin, const float* __restrict__ blin) {
    int idx = blockIdx.x * blockDim.x + threadIdx.x;
    if (idx < HID * F_OUT) {
        int k = idx / F_OUT, o = idx - k * F_OUT;
        float s = 0.f;
#pragma unroll 8
        for (int m = 0; m < HID; m++) s = fmaf(W2[k * HID + m], Wlin[m * F_OUT + o], s);
        g_Wc[idx] = s;
    } else if (idx < HID * F_OUT + F_OUT) {
        int o = idx - HID * F_OUT;
        float s = blin[o];
#pragma unroll 8
        for (int m = 0; m < HID; m++) s = fmaf(b2[m], Wlin[m * F_OUT + o], s);
        g_bc[o] = s;
    }
}

// ---- fused layer-2 aggregation + mean-pool accumulation ----
// warp handles 8 consecutive nodes; 16-lane half-warps process 2 edges/step;
// lane owns 8 features (one LDG.128 per gather). Run-length merge by sorted batch.
__global__ void __launch_bounds__(256) k_aggpool(const int* __restrict__ batch) {
    int tid = threadIdx.x;
    int wi = tid >> 5, l = tid & 31;
    int group = l >> 4;            // 0: even edges, 1: odd edges
    int fl = (l & 15) * 8;         // feature base (8 halves)
    int node0 = blockIdx.x * 64 + wi * 8;

    int gprev = -1;
    float r0 = 0.f, r1 = 0.f, r2 = 0.f, r3 = 0.f;
    int fbase = fl + group * 4;    // this lane's 4-atomic feature base

#pragma unroll 1
    for (int i = 0; i < 8; i++) {
        int node = node0 + i;
        if (node >= N_NODES) break;
        float a0, a1, a2, a3, a4, a5, a6, a7;
        {
            float di = g_dinv[node];
            float selfw = (group == 0) ? di * di : 0.f;
            uint4 hs = *(const uint4*)&g_h1h[node * HID + fl];
            float2 s01 = __half22float2(*(__half2*)&hs.x);
            float2 s23 = __half22float2(*(__half2*)&hs.y);
            float2 s45 = __half22float2(*(__half2*)&hs.z);
            float2 s67 = __half22float2(*(__half2*)&hs.w);
            a0 = s01.x * selfw; a1 = s01.y * selfw;
            a2 = s23.x * selfw; a3 = s23.y * selfw;
            a4 = s45.x * selfw; a5 = s45.y * selfw;
            a6 = s67.x * selfw; a7 = s67.y * selfw;
        }
        int rs = g_rowptr[node], re = g_rowptr[node + 1];
        for (int e0 = rs; e0 < re; e0 += 32) {
            int ec = min(32, re - e0);
            int2 cw = make_int2(0, 0);                 // w bits 0 -> 0.0f (safe pad)
            if (e0 + l < re) cw = g_csr2[e0 + l];
            int jmax = (ec + 1) >> 1;
#pragma unroll 4
            for (int j = 0; j < jmax; j++) {
                int sl = 2 * j + group;
                int s = __shfl_sync(0xffffffffu, cw.x, sl);
                float w = __int_as_float(__shfl_sync(0xffffffffu, cw.y, sl));
                uint4 hv = *(const uint4*)&g_h1h[s * HID + fl];
                float2 h01 = __half22float2(*(__half2*)&hv.x);
                float2 h23 = __half22float2(*(__half2*)&hv.y);
                float2 h45 = __half22float2(*(__half2*)&hv.z);
                float2 h67 = __half22float2(*(__half2*)&hv.w);
                a0 = fmaf(h01.x, w, a0); a1 = fmaf(h01.y, w, a1);
                a2 = fmaf(h23.x, w, a2); a3 = fmaf(h23.y, w, a3);
                a4 = fmaf(h45.x, w, a4); a5 = fmaf(h45.y, w, a5);
                a6 = fmaf(h67.x, w, a6); a7 = fmaf(h67.y, w, a7);
            }
        }
        // combine even/odd edge halves (lanes l and l^16 hold same features)
        a0 += __shfl_xor_sync(0xffffffffu, a0, 16);
        a1 += __shfl_xor_sync(0xffffffffu, a1, 16);
        a2 += __shfl_xor_sync(0xffffffffu, a2, 16);
        a3 += __shfl_xor_sync(0xffffffffu, a3, 16);
        a4 += __shfl_xor_sync(0xffffffffu, a4, 16);
        a5 += __shfl_xor_sync(0xffffffffu, a5, 16);
        a6 += __shfl_xor_sync(0xffffffffu, a6, 16);
        a7 += __shfl_xor_sync(0xffffffffu, a7, 16);
        // lane's 4 features: group0 -> a0..a3, group1 -> a4..a7
        float v0 = group ? a4 : a0;
        float v1 = group ? a5 : a1;
        float v2 = group ? a6 : a2;
        float v3 = group ? a7 : a3;

        int g = batch[node];
        if (g != gprev) {
            if (gprev >= 0) {
                atomicAdd(&g_q[gprev * HID + fbase + 0], r0);
                atomicAdd(&g_q[gprev * HID + fbase + 1], r1);
                atomicAdd(&g_q[gprev * HID + fbase + 2], r2);
                atomicAdd(&g_q[gprev * HID + fbase + 3], r3);
            }
            gprev = g; r0 = r1 = r2 = r3 = 0.f;
        }
        r0 += v0; r1 += v1; r2 += v2; r3 += v3;
    }
    if (gprev >= 0) {
        atomicAdd(&g_q[gprev * HID + fbase + 0], r0);
        atomicAdd(&g_q[gprev * HID + fbase + 1], r1);
        atomicAdd(&g_q[gprev * HID + fbase + 2], r2);
        atomicAdd(&g_q[gprev * HID + fbase + 3], r3);
    }
}

// out[g] = (q[g] @ Wc) / max(cnt,1) + bc
__global__ void k_final(float* __restrict__ out) {
    int g = blockIdx.x;
    int o = threadIdx.x;
    __shared__ float sp[HID];
    for (int k = o; k < HID; k += 32) sp[k] = g_q[g * HID + k];
    __syncthreads();
    float inv = 1.f / fmaxf(g_gcnt[g], 1.f);
    if (o < F_OUT) {
        float acc = 0.f;
#pragma unroll 8
        for (int k = 0; k < HID; k++) acc = fmaf(sp[k], g_Wc[k * F_OUT + o], acc);
        out[g * F_OUT + o] = acc * inv + g_bc[o];
    }
}

// ---------------- launch ----------------
extern "C" void kernel_launch(void* const* d_in, const int* in_sizes, int n_in,
                              void* d_out, int out_size) {
    const float* x    = (const float*)d_in[0];
    const int*   esrc = (const int*)d_in[1];
    const int*   edst = (const int*)d_in[2];
    const int*   batch= (const int*)d_in[3];
    const float* W1   = (const float*)d_in[4];
    const float* b1   = (const float*)d_in[5];
    const float* W2   = (const float*)d_in[6];
    const float* b2   = (const float*)d_in[7];
    const float* Wlin = (const float*)d_in[8];
    const float* blin = (const float*)d_in[9];
    float* out = (float*)d_out;

    k_zero<<<512, 256>>>();
    k_padx<<<1024, 256>>>(x);
    k_wc<<<(HID * F_OUT + F_OUT + 255) / 256, 256>>>(W2, b2, Wlin, blin);
    k_count<<<2048, 256>>>(edst, batch);
    k_scan1<<<SCAN_NBLK, 1024>>>();
    k_scan2<<<1, 64>>>();
    k_scan3<<<(N_NODES + 255) / 256, 256>>>();
    k_fill<<<2048, 256>>>(esrc, edst);
    k_agg1<<<(N_NODES + 127) / 128, 128>>>();
    k_gemm1<<<1024, 256>>>(W1, b1);
    k_aggpool<<<(N_NODES + 63) / 64, 256>>>(batch);
    k_final<<<NUM_GRAPHS, 32>>>(out);
}

// round 7
// speedup vs baseline: 4.5322x; 1.0575x over previous
#include <cuda_runtime.h>
#include <cuda_fp16.h>

#define N_NODES 100000
#define N_EDGES 1600000
#define NUM_GRAPHS 4096
#define HID 128
#define F_IN 11
#define F_PAD 12
#define F_OUT 19

#define SCAN_CHUNK 2048
#define SCAN_NBLK ((N_NODES + SCAN_CHUNK - 1) / SCAN_CHUNK)   // 49

// ---------------- scratch (static device globals; no allocation) ----------------
__device__ int    g_cnt[N_NODES];
__device__ int    g_fill[N_NODES];
__device__ float  g_dinv[N_NODES];
__device__ int    g_rowptr[N_NODES + 1];
__device__ int2   g_csr2[N_EDGES];            // {src, norm as float bits}
__device__ float  g_x12[N_NODES * F_PAD];     // x padded to 12 floats/row
__device__ __half g_h1h[N_NODES * HID];       // fp16 h1
__device__ float  g_q[NUM_GRAPHS * HID];      // pooled aggregated features
__device__ float  g_gcnt[NUM_GRAPHS];
__device__ float  g_Wc[HID * F_OUT];          // W2 @ Wlin
__device__ float  g_bc[F_OUT];                // b2 @ Wlin + blin
__device__ int    g_bsum[64];

// ---------------- kernels ----------------

// init: zero counters/accumulators, pad x to 12 floats, precompute Wc/bc
__global__ void k_init(const float* __restrict__ x,
                       const float* __restrict__ W2, const float* __restrict__ b2,
                       const float* __restrict__ Wlin, const float* __restrict__ blin) {
    int i = blockIdx.x * blockDim.x + threadIdx.x;
    int stride = gridDim.x * blockDim.x;
    for (int j = i; j < N_NODES; j += stride) { g_cnt[j] = 0; g_fill[j] = 0; }
    for (int j = i; j < NUM_GRAPHS * HID; j += stride) g_q[j] = 0.f;
    for (int j = i; j < NUM_GRAPHS; j += stride) g_gcnt[j] = 0.f;
    for (int j = i; j < N_NODES * F_PAD; j += stride) {
        int n = j / F_PAD, f = j - n * F_PAD;
        g_x12[j] = (f < F_IN) ? x[n * F_IN + f] : 0.f;
    }
    // Wc = W2 @ Wlin ; bc = b2 @ Wlin + blin
    for (int j = i; j < HID * F_OUT + F_OUT; j += stride) {
        if (j < HID * F_OUT) {
            int k = j / F_OUT, o = j - k * F_OUT;
            float s = 0.f;
#pragma unroll 8
            for (int m = 0; m < HID; m++) s = fmaf(W2[k * HID + m], Wlin[m * F_OUT + o], s);
            g_Wc[j] = s;
        } else {
            int o = j - HID * F_OUT;
            float s = blin[o];
#pragma unroll 8
            for (int m = 0; m < HID; m++) s = fmaf(b2[m], Wlin[m * F_OUT + o], s);
            g_bc[o] = s;
        }
    }
}

// edge in-degree count + per-graph node count (int4 vectorized)
__global__ void k_count(const int* __restrict__ dst, const int* __restrict__ batch) {
    int i = blockIdx.x * blockDim.x + threadIdx.x;
    int stride = gridDim.x * blockDim.x;
    const int4* dst4 = (const int4*)dst;
    for (int e = i; e < N_EDGES / 4; e += stride) {
        int4 d = dst4[e];
        atomicAdd(&g_cnt[d.x], 1);
        atomicAdd(&g_cnt[d.y], 1);
        atomicAdd(&g_cnt[d.z], 1);
        atomicAdd(&g_cnt[d.w], 1);
    }
    const int4* b4 = (const int4*)batch;
    for (int n = i; n < N_NODES / 4; n += stride) {
        int4 b = b4[n];
        if (b.x == b.w) {                       // sorted: all 4 equal
            atomicAdd(&g_gcnt[b.x], 4.f);
        } else {
            atomicAdd(&g_gcnt[b.x], 1.f);
            atomicAdd(&g_gcnt[b.y], 1.f);
            atomicAdd(&g_gcnt[b.z], 1.f);
            atomicAdd(&g_gcnt[b.w], 1.f);
        }
    }
}

// ---- scan phase 1 (+ dinv fused) ----
__global__ void k_scan1() {
    __shared__ int sm[1024];
    int t = threadIdx.x;
    int base = blockIdx.x * SCAN_CHUNK;
    int i0 = base + 2 * t, i1 = i0 + 1;
    int v0 = (i0 < N_NODES) ? g_cnt[i0] : 0;
    int v1 = (i1 < N_NODES) ? g_cnt[i1] : 0;
    if (i0 < N_NODES) g_dinv[i0] = rsqrtf((float)(v0 + 1));
    if (i1 < N_NODES) g_dinv[i1] = rsqrtf((float)(v1 + 1));
    int s = v0 + v1;
    sm[t] = s;
    __syncthreads();
    for (int off = 1; off < 1024; off <<= 1) {
        int add = (t >= off) ? sm[t - off] : 0;
        __syncthreads();
        sm[t] += add;
        __syncthreads();
    }
    int excl = sm[t] - s;
    if (i0 < N_NODES) g_rowptr[i0] = excl;
    if (i1 < N_NODES) g_rowptr[i1] = excl + v0;
    if (t == 1023) g_bsum[blockIdx.x] = sm[t];
}

// ---- scan phases 2+3 merged: each block redundantly scans the 49 partials ----
__global__ void k_scan23() {
    __shared__ int sm[64];
    int t = threadIdx.x;
    if (t < 64) sm[t] = (t < SCAN_NBLK) ? g_bsum[t] : 0;
    __syncthreads();
    if (t == 0) {
        int run = 0;
#pragma unroll
        for (int j = 0; j < SCAN_NBLK; j++) { int v = sm[j]; sm[j] = run; run += v; }
    }
    __syncthreads();
    int i = blockIdx.x * blockDim.x + t;
    if (i < N_NODES) g_rowptr[i] += sm[i >> 11];
    if (i == 0) g_rowptr[N_NODES] = N_EDGES;
}

// CSR fill (int4 vectorized edge reads)
__global__ void k_fill(const int* __restrict__ src, const int* __restrict__ dst) {
    int i = blockIdx.x * blockDim.x + threadIdx.x;
    int stride = gridDim.x * blockDim.x;
    const int4* src4 = (const int4*)src;
    const int4* dst4 = (const int4*)dst;
    for (int e = i; e < N_EDGES / 4; e += stride) {
        int4 s = src4[e];
        int4 d = dst4[e];
        {
            int pos = g_rowptr[d.x] + atomicAdd(&g_fill[d.x], 1);
            g_csr2[pos] = make_int2(s.x, __float_as_int(g_dinv[s.x] * g_dinv[d.x]));
        }
        {
            int pos = g_rowptr[d.y] + atomicAdd(&g_fill[d.y], 1);
            g_csr2[pos] = make_int2(s.y, __float_as_int(g_dinv[s.y] * g_dinv[d.y]));
        }
        {
            int pos = g_rowptr[d.z] + atomicAdd(&g_fill[d.z], 1);
            g_csr2[pos] = make_int2(s.z, __float_as_int(g_dinv[s.z] * g_dinv[d.z]));
        }
        {
            int pos = g_rowptr[d.w] + atomicAdd(&g_fill[d.w], 1);
            g_csr2[pos] = make_int2(s.w, __float_as_int(g_dinv[s.w] * g_dinv[d.w]));
        }
    }
}

// ---- fused layer 1: per-node aggregation of x12 -> smem -> warp GEMM -> fp16 h1 ----
// block = 128 threads; thread aggregates one node; then each warp GEMMs 32 nodes
__global__ void __launch_bounds__(128) k_layer1(const float* __restrict__ W1,
                                                const float* __restrict__ b1) {
    __shared__ float sw[F_IN][HID];
    __shared__ float sb[HID];
    __shared__ float sa[128][13];
    int tid = threadIdx.x;
    for (int j = tid; j < F_IN * HID; j += 128) sw[j / HID][j % HID] = W1[j];
    for (int j = tid; j < HID; j += 128) sb[j] = b1[j];

    int node = blockIdx.x * 128 + tid;
    if (node < N_NODES) {
        float di = g_dinv[node];
        float selfw = di * di;
        float4 a0 = *(const float4*)&g_x12[node * F_PAD];
        float4 a1 = *(const float4*)&g_x12[node * F_PAD + 4];
        float4 a2 = *(const float4*)&g_x12[node * F_PAD + 8];
        a0.x *= selfw; a0.y *= selfw; a0.z *= selfw; a0.w *= selfw;
        a1.x *= selfw; a1.y *= selfw; a1.z *= selfw; a1.w *= selfw;
        a2.x *= selfw; a2.y *= selfw; a2.z *= selfw;
        int rs = g_rowptr[node], re = g_rowptr[node + 1];
#pragma unroll 2
        for (int e = rs; e < re; e++) {
            int2 cw = g_csr2[e];
            int s = cw.x;
            float w = __int_as_float(cw.y);
            float4 x0 = *(const float4*)&g_x12[s * F_PAD];
            float4 x1 = *(const float4*)&g_x12[s * F_PAD + 4];
            float4 x2 = *(const float4*)&g_x12[s * F_PAD + 8];
            a0.x = fmaf(x0.x, w, a0.x); a0.y = fmaf(x0.y, w, a0.y);
            a0.z = fmaf(x0.z, w, a0.z); a0.w = fmaf(x0.w, w, a0.w);
            a1.x = fmaf(x1.x, w, a1.x); a1.y = fmaf(x1.y, w, a1.y);
            a1.z = fmaf(x1.z, w, a1.z); a1.w = fmaf(x1.w, w, a1.w);
            a2.x = fmaf(x2.x, w, a2.x); a2.y = fmaf(x2.y, w, a2.y);
            a2.z = fmaf(x2.z, w, a2.z);
        }
        sa[tid][0] = a0.x; sa[tid][1] = a0.y; sa[tid][2]  = a0.z; sa[tid][3]  = a0.w;
        sa[tid][4] = a1.x; sa[tid][5] = a1.y; sa[tid][6]  = a1.z; sa[tid][7]  = a1.w;
        sa[tid][8] = a2.x; sa[tid][9] = a2.y; sa[tid][10] = a2.z;
    }
    __syncthreads();

    int wi = tid >> 5, l = tid & 31;
    int f = l * 4;
    float4 bias = *(const float4*)&sb[f];
#pragma unroll 4
    for (int i = 0; i < 32; i++) {
        int nn = wi * 32 + i;
        int nd = blockIdx.x * 128 + nn;
        if (nd >= N_NODES) break;
        float4 acc = bias;
#pragma unroll
        for (int k = 0; k < F_IN; k++) {
            float a = sa[nn][k];
            float4 w = *(const float4*)&sw[k][f];
            acc.x = fmaf(a, w.x, acc.x);
            acc.y = fmaf(a, w.y, acc.y);
            acc.z = fmaf(a, w.z, acc.z);
            acc.w = fmaf(a, w.w, acc.w);
        }
        uint2 st;
        *(__half2*)&st.x = __floats2half2_rn(fmaxf(acc.x, 0.f), fmaxf(acc.y, 0.f));
        *(__half2*)&st.y = __floats2half2_rn(fmaxf(acc.z, 0.f), fmaxf(acc.w, 0.f));
        *(uint2*)&g_h1h[nd * HID + f] = st;
    }
}

// ---- fused layer-2 aggregation + mean-pool accumulation ----
__global__ void __launch_bounds__(256) k_aggpool(const int* __restrict__ batch) {
    int tid = threadIdx.x;
    int wi = tid >> 5, l = tid & 31;
    int group = l >> 4;            // 0: even edges, 1: odd edges
    int fl = (l & 15) * 8;         // feature base (8 halves)
    int node0 = blockIdx.x * 64 + wi * 8;

    int gprev = -1;
    float r0 = 0.f, r1 = 0.f, r2 = 0.f, r3 = 0.f;
    int fbase = fl + group * 4;

#pragma unroll 1
    for (int i = 0; i < 8; i++) {
        int node = node0 + i;
        if (node >= N_NODES) break;
        float a0, a1, a2, a3, a4, a5, a6, a7;
        {
            float di = g_dinv[node];
            float selfw = (group == 0) ? di * di : 0.f;
            uint4 hs = *(const uint4*)&g_h1h[node * HID + fl];
            float2 s01 = __half22float2(*(__half2*)&hs.x);
            float2 s23 = __half22float2(*(__half2*)&hs.y);
            float2 s45 = __half22float2(*(__half2*)&hs.z);
            float2 s67 = __half22float2(*(__half2*)&hs.w);
            a0 = s01.x * selfw; a1 = s01.y * selfw;
            a2 = s23.x * selfw; a3 = s23.y * selfw;
            a4 = s45.x * selfw; a5 = s45.y * selfw;
            a6 = s67.x * selfw; a7 = s67.y * selfw;
        }
        int rs = g_rowptr[node], re = g_rowptr[node + 1];
        for (int e0 = rs; e0 < re; e0 += 32) {
            int ec = min(32, re - e0);
            int2 cw = make_int2(0, 0);
            if (e0 + l < re) cw = g_csr2[e0 + l];
            int jmax = (ec + 1) >> 1;
#pragma unroll 4
            for (int j = 0; j < jmax; j++) {
                int sl = 2 * j + group;
                int s = __shfl_sync(0xffffffffu, cw.x, sl);
                float w = __int_as_float(__shfl_sync(0xffffffffu, cw.y, sl));
                uint4 hv = *(const uint4*)&g_h1h[s * HID + fl];
                float2 h01 = __half22float2(*(__half2*)&hv.x);
                float2 h23 = __half22float2(*(__half2*)&hv.y);
                float2 h45 = __half22float2(*(__half2*)&hv.z);
                float2 h67 = __half22float2(*(__half2*)&hv.w);
                a0 = fmaf(h01.x, w, a0); a1 = fmaf(h01.y, w, a1);
                a2 = fmaf(h23.x, w, a2); a3 = fmaf(h23.y, w, a3);
                a4 = fmaf(h45.x, w, a4); a5 = fmaf(h45.y, w, a5);
                a6 = fmaf(h67.x, w, a6); a7 = fmaf(h67.y, w, a7);
            }
        }
        a0 += __shfl_xor_sync(0xffffffffu, a0, 16);
        a1 += __shfl_xor_sync(0xffffffffu, a1, 16);
        a2 += __shfl_xor_sync(0xffffffffu, a2, 16);
        a3 += __shfl_xor_sync(0xffffffffu, a3, 16);
        a4 += __shfl_xor_sync(0xffffffffu, a4, 16);
        a5 += __shfl_xor_sync(0xffffffffu, a5, 16);
        a6 += __shfl_xor_sync(0xffffffffu, a6, 16);
        a7 += __shfl_xor_sync(0xffffffffu, a7, 16);
        float v0 = group ? a4 : a0;
        float v1 = group ? a5 : a1;
        float v2 = group ? a6 : a2;
        float v3 = group ? a7 : a3;

        int g = batch[node];
        if (g != gprev) {
            if (gprev >= 0) {
                atomicAdd(&g_q[gprev * HID + fbase + 0], r0);
                atomicAdd(&g_q[gprev * HID + fbase + 1], r1);
                atomicAdd(&g_q[gprev * HID + fbase + 2], r2);
                atomicAdd(&g_q[gprev * HID + fbase + 3], r3);
            }
            gprev = g; r0 = r1 = r2 = r3 = 0.f;
        }
        r0 += v0; r1 += v1; r2 += v2; r3 += v3;
    }
    if (gprev >= 0) {
        atomicAdd(&g_q[gprev * HID + fbase + 0], r0);
        atomicAdd(&g_q[gprev * HID + fbase + 1], r1);
        atomicAdd(&g_q[gprev * HID + fbase + 2], r2);
        atomicAdd(&g_q[gprev * HID + fbase + 3], r3);
    }
}

// out[g] = (q[g] @ Wc) / max(cnt,1) + bc
__global__ void k_final(float* __restrict__ out) {
    int g = blockIdx.x;
    int o = threadIdx.x;
    __shared__ float sp[HID];
    for (int k = o; k < HID; k += 32) sp[k] = g_q[g * HID + k];
    __syncthreads();
    float inv = 1.f / fmaxf(g_gcnt[g], 1.f);
    if (o < F_OUT) {
        float acc = 0.f;
#pragma unroll 8
        for (int k = 0; k < HID; k++) acc = fmaf(sp[k], g_Wc[k * F_OUT + o], acc);
        out[g * F_OUT + o] = acc * inv + g_bc[o];
    }
}

// ---------------- launch ----------------
extern "C" void kernel_launch(void* const* d_in, const int* in_sizes, int n_in,
                              void* d_out, int out_size) {
    const float* x    = (const float*)d_in[0];
    const int*   esrc = (const int*)d_in[1];
    const int*   edst = (const int*)d_in[2];
    const int*   batch= (const int*)d_in[3];
    const float* W1   = (const float*)d_in[4];
    const float* b1   = (const float*)d_in[5];
    const float* W2   = (const float*)d_in[6];
    const float* b2   = (const float*)d_in[7];
    const float* Wlin = (const float*)d_in[8];
    const float* blin = (const float*)d_in[9];
    float* out = (float*)d_out;

    k_init<<<1024, 256>>>(x, W2, b2, Wlin, blin);
    k_count<<<512, 256>>>(edst, batch);
    k_scan1<<<SCAN_NBLK, 1024>>>();
    k_scan23<<<(N_NODES + 255) / 256, 256>>>();
    k_fill<<<1024, 256>>>(esrc, edst);
    k_layer1<<<(N_NODES + 127) / 128, 128>>>(W1, b1);
    k_aggpool<<<(N_NODES + 63) / 64, 256>>>(batch);
    k_final<<<NUM_GRAPHS, 32>>>(out);
}

// round 8
// speedup vs baseline: 5.0725x; 1.1192x over previous
#include <cuda_runtime.h>
#include <cuda_fp16.h>

#define N_NODES 100000
#define N_EDGES 1600000
#define NUM_GRAPHS 4096
#define HID 128
#define F_IN 11
#define F_PAD 12
#define F_OUT 19

#define SCAN_CHUNK 2048
#define SCAN_NBLK ((N_NODES + SCAN_CHUNK - 1) / SCAN_CHUNK)   // 49

// ---------------- scratch (static device globals; no allocation) ----------------
__device__ int    g_cnt[N_NODES];
__device__ int    g_fill[N_NODES];
__device__ float  g_dinv[N_NODES];
__device__ int    g_rowptr[N_NODES + 1];
__device__ int    g_csr[N_EDGES];                  // src only
__device__ float  g_x12[N_NODES * F_PAD];          // x * dinv, padded to 12
__device__ __half g_h1h[(N_NODES + 1) * HID];      // h1' = relu(h1)*dinv; last row = 0 sentinel
__device__ float  g_q[NUM_GRAPHS * HID];
__device__ float  g_gcnt[NUM_GRAPHS];
__device__ float  g_Wc[HID * F_OUT];
__device__ float  g_bc[F_OUT];
__device__ int    g_bsum[64];

// ---------------- kernels ----------------

// init: zero counters/accumulators + sentinel h1 row, precompute Wc/bc
__global__ void k_init(const float* __restrict__ W2, const float* __restrict__ b2,
                       const float* __restrict__ Wlin, const float* __restrict__ blin) {
    int i = blockIdx.x * blockDim.x + threadIdx.x;
    int stride = gridDim.x * blockDim.x;
    for (int j = i; j < N_NODES; j += stride) { g_cnt[j] = 0; g_fill[j] = 0; }
    for (int j = i; j < NUM_GRAPHS * HID; j += stride) g_q[j] = 0.f;
    for (int j = i; j < NUM_GRAPHS; j += stride) g_gcnt[j] = 0.f;
    for (int j = i; j < HID; j += stride)
        g_h1h[N_NODES * HID + j] = __float2half_rn(0.f);   // sentinel row
    for (int j = i; j < HID * F_OUT + F_OUT; j += stride) {
        if (j < HID * F_OUT) {
            int k = j / F_OUT, o = j - k * F_OUT;
            float s = 0.f;
#pragma unroll 8
            for (int m = 0; m < HID; m++) s = fmaf(W2[k * HID + m], Wlin[m * F_OUT + o], s);
            g_Wc[j] = s;
        } else {
            int o = j - HID * F_OUT;
            float s = blin[o];
#pragma unroll 8
            for (int m = 0; m < HID; m++) s = fmaf(b2[m], Wlin[m * F_OUT + o], s);
            g_bc[o] = s;
        }
    }
}

// edge in-degree count + per-graph node count (int4 vectorized)
__global__ void k_count(const int* __restrict__ dst, const int* __restrict__ batch) {
    int i = blockIdx.x * blockDim.x + threadIdx.x;
    int stride = gridDim.x * blockDim.x;
    const int4* dst4 = (const int4*)dst;
    for (int e = i; e < N_EDGES / 4; e += stride) {
        int4 d = dst4[e];
        atomicAdd(&g_cnt[d.x], 1);
        atomicAdd(&g_cnt[d.y], 1);
        atomicAdd(&g_cnt[d.z], 1);
        atomicAdd(&g_cnt[d.w], 1);
    }
    const int4* b4 = (const int4*)batch;
    for (int n = i; n < N_NODES / 4; n += stride) {
        int4 b = b4[n];
        if (b.x == b.w) {
            atomicAdd(&g_gcnt[b.x], 4.f);
        } else {
            atomicAdd(&g_gcnt[b.x], 1.f);
            atomicAdd(&g_gcnt[b.y], 1.f);
            atomicAdd(&g_gcnt[b.z], 1.f);
            atomicAdd(&g_gcnt[b.w], 1.f);
        }
    }
}

// ---- scan phase 1 (+ dinv fused) ----
__global__ void k_scan1() {
    __shared__ int sm[1024];
    int t = threadIdx.x;
    int base = blockIdx.x * SCAN_CHUNK;
    int i0 = base + 2 * t, i1 = i0 + 1;
    int v0 = (i0 < N_NODES) ? g_cnt[i0] : 0;
    int v1 = (i1 < N_NODES) ? g_cnt[i1] : 0;
    if (i0 < N_NODES) g_dinv[i0] = rsqrtf((float)(v0 + 1));
    if (i1 < N_NODES) g_dinv[i1] = rsqrtf((float)(v1 + 1));
    int s = v0 + v1;
    sm[t] = s;
    __syncthreads();
    for (int off = 1; off < 1024; off <<= 1) {
        int add = (t >= off) ? sm[t - off] : 0;
        __syncthreads();
        sm[t] += add;
        __syncthreads();
    }
    int excl = sm[t] - s;
    if (i0 < N_NODES) g_rowptr[i0] = excl;
    if (i1 < N_NODES) g_rowptr[i1] = excl + v0;
    if (t == 1023) g_bsum[blockIdx.x] = sm[t];
}

// ---- scan phases 2+3 merged ----
__global__ void k_scan23() {
    __shared__ int sm[64];
    int t = threadIdx.x;
    if (t < 64) sm[t] = (t < SCAN_NBLK) ? g_bsum[t] : 0;
    __syncthreads();
    if (t == 0) {
        int run = 0;
#pragma unroll
        for (int j = 0; j < SCAN_NBLK; j++) { int v = sm[j]; sm[j] = run; run += v; }
    }
    __syncthreads();
    int i = blockIdx.x * blockDim.x + t;
    if (i < N_NODES) g_rowptr[i] += sm[i >> 11];
    if (i == 0) g_rowptr[N_NODES] = N_EDGES;
}

// CSR fill (src only, int4 reads) + build x12 = x * dinv (padded)
__global__ void k_fill(const int* __restrict__ src, const int* __restrict__ dst,
                       const float* __restrict__ x) {
    int i = blockIdx.x * blockDim.x + threadIdx.x;
    int stride = gridDim.x * blockDim.x;
    const int4* src4 = (const int4*)src;
    const int4* dst4 = (const int4*)dst;
    for (int e = i; e < N_EDGES / 4; e += stride) {
        int4 s = src4[e];
        int4 d = dst4[e];
        g_csr[g_rowptr[d.x] + atomicAdd(&g_fill[d.x], 1)] = s.x;
        g_csr[g_rowptr[d.y] + atomicAdd(&g_fill[d.y], 1)] = s.y;
        g_csr[g_rowptr[d.z] + atomicAdd(&g_fill[d.z], 1)] = s.z;
        g_csr[g_rowptr[d.w] + atomicAdd(&g_fill[d.w], 1)] = s.w;
    }
    for (int n = i; n < N_NODES; n += stride) {
        float di = g_dinv[n];
        float r[F_PAD];
#pragma unroll
        for (int f = 0; f < F_IN; f++) r[f] = x[n * F_IN + f] * di;
        r[11] = 0.f;
        *(float4*)&g_x12[n * F_PAD]     = make_float4(r[0], r[1], r[2],  r[3]);
        *(float4*)&g_x12[n * F_PAD + 4] = make_float4(r[4], r[5], r[6],  r[7]);
        *(float4*)&g_x12[n * F_PAD + 8] = make_float4(r[8], r[9], r[10], r[11]);
    }
}

// ---- fused layer 1: aggregate x' -> *dinv -> smem -> warp GEMM -> relu*dinv -> fp16 ----
__global__ void __launch_bounds__(128) k_layer1(const float* __restrict__ W1,
                                                const float* __restrict__ b1) {
    __shared__ float sw[F_IN][HID];
    __shared__ float sb[HID];
    __shared__ float sa[128][13];
    __shared__ float sdi[128];
    int tid = threadIdx.x;
    for (int j = tid; j < F_IN * HID; j += 128) sw[j / HID][j % HID] = W1[j];
    for (int j = tid; j < HID; j += 128) sb[j] = b1[j];

    int node = blockIdx.x * 128 + tid;
    if (node < N_NODES) {
        float di = g_dinv[node];
        sdi[tid] = di;
        float4 a0 = *(const float4*)&g_x12[node * F_PAD];       // self term (pre-scaled)
        float4 a1 = *(const float4*)&g_x12[node * F_PAD + 4];
        float4 a2 = *(const float4*)&g_x12[node * F_PAD + 8];
        int rs = g_rowptr[node], re = g_rowptr[node + 1];
#pragma unroll 2
        for (int e = rs; e < re; e++) {
            int s = g_csr[e];
            float4 x0 = *(const float4*)&g_x12[s * F_PAD];
            float4 x1 = *(const float4*)&g_x12[s * F_PAD + 4];
            float4 x2 = *(const float4*)&g_x12[s * F_PAD + 8];
            a0.x += x0.x; a0.y += x0.y; a0.z += x0.z; a0.w += x0.w;
            a1.x += x1.x; a1.y += x1.y; a1.z += x1.z; a1.w += x1.w;
            a2.x += x2.x; a2.y += x2.y; a2.z += x2.z;
        }
        sa[tid][0] = a0.x * di; sa[tid][1] = a0.y * di; sa[tid][2]  = a0.z * di; sa[tid][3] = a0.w * di;
        sa[tid][4] = a1.x * di; sa[tid][5] = a1.y * di; sa[tid][6]  = a1.z * di; sa[tid][7] = a1.w * di;
        sa[tid][8] = a2.x * di; sa[tid][9] = a2.y * di; sa[tid][10] = a2.z * di;
    }
    __syncthreads();

    int wi = tid >> 5, l = tid & 31;
    int f = l * 4;
    float4 bias = *(const float4*)&sb[f];
#pragma unroll 4
    for (int i = 0; i < 32; i++) {
        int nn = wi * 32 + i;
        int nd = blockIdx.x * 128 + nn;
        if (nd >= N_NODES) break;
        float4 acc = bias;
#pragma unroll
        for (int k = 0; k < F_IN; k++) {
            float a = sa[nn][k];
            float4 w = *(const float4*)&sw[k][f];
            acc.x = fmaf(a, w.x, acc.x);
            acc.y = fmaf(a, w.y, acc.y);
            acc.z = fmaf(a, w.z, acc.z);
            acc.w = fmaf(a, w.w, acc.w);
        }
        float di = sdi[nn];
        uint2 st;
        *(__half2*)&st.x = __floats2half2_rn(fmaxf(acc.x, 0.f) * di, fmaxf(acc.y, 0.f) * di);
        *(__half2*)&st.y = __floats2half2_rn(fmaxf(acc.z, 0.f) * di, fmaxf(acc.w, 0.f) * di);
        *(uint2*)&g_h1h[nd * HID + f] = st;
    }
}

// ---- fused layer-2 aggregation + mean-pool accumulation (no per-edge norm) ----
__global__ void __launch_bounds__(256) k_aggpool(const int* __restrict__ batch) {
    int tid = threadIdx.x;
    int wi = tid >> 5, l = tid & 31;
    int group = l >> 4;
    int fl = (l & 15) * 8;
    int node0 = blockIdx.x * 64 + wi * 8;

    int gprev = -1;
    float r0 = 0.f, r1 = 0.f, r2 = 0.f, r3 = 0.f;
    int fbase = fl + group * 4;

#pragma unroll 1
    for (int i = 0; i < 8; i++) {
        int node = node0 + i;
        if (node >= N_NODES) break;
        float a0, a1, a2, a3, a4, a5, a6, a7;
        {
            // self term: h1'[node], weight 1 (final *dinv applied in epilogue)
            float sw0 = (group == 0) ? 1.f : 0.f;
            uint4 hs = *(const uint4*)&g_h1h[node * HID + fl];
            float2 s01 = __half22float2(*(__half2*)&hs.x);
            float2 s23 = __half22float2(*(__half2*)&hs.y);
            float2 s45 = __half22float2(*(__half2*)&hs.z);
            float2 s67 = __half22float2(*(__half2*)&hs.w);
            a0 = s01.x * sw0; a1 = s01.y * sw0;
            a2 = s23.x * sw0; a3 = s23.y * sw0;
            a4 = s45.x * sw0; a5 = s45.y * sw0;
            a6 = s67.x * sw0; a7 = s67.y * sw0;
        }
        int rs = g_rowptr[node], re = g_rowptr[node + 1];
        for (int e0 = rs; e0 < re; e0 += 32) {
            int ec = min(32, re - e0);
            int cs = (e0 + l < re) ? g_csr[e0 + l] : N_NODES;   // sentinel -> zero row
            int jmax = (ec + 1) >> 1;
#pragma unroll 4
            for (int j = 0; j < jmax; j++) {
                int sl = 2 * j + group;
                int s = __shfl_sync(0xffffffffu, cs, sl);
                uint4 hv = *(const uint4*)&g_h1h[s * HID + fl];
                float2 h01 = __half22float2(*(__half2*)&hv.x);
                float2 h23 = __half22float2(*(__half2*)&hv.y);
                float2 h45 = __half22float2(*(__half2*)&hv.z);
                float2 h67 = __half22float2(*(__half2*)&hv.w);
                a0 += h01.x; a1 += h01.y;
                a2 += h23.x; a3 += h23.y;
                a4 += h45.x; a5 += h45.y;
                a6 += h67.x; a7 += h67.y;
            }
        }
        a0 += __shfl_xor_sync(0xffffffffu, a0, 16);
        a1 += __shfl_xor_sync(0xffffffffu, a1, 16);
        a2 += __shfl_xor_sync(0xffffffffu, a2, 16);
        a3 += __shfl_xor_sync(0xffffffffu, a3, 16);
        a4 += __shfl_xor_sync(0xffffffffu, a4, 16);
        a5 += __shfl_xor_sync(0xffffffffu, a5, 16);
        a6 += __shfl_xor_sync(0xffffffffu, a6, 16);
        a7 += __shfl_xor_sync(0xffffffffu, a7, 16);
        float di = g_dinv[node];
        float v0 = (group ? a4 : a0) * di;
        float v1 = (group ? a5 : a1) * di;
        float v2 = (group ? a6 : a2) * di;
        float v3 = (group ? a7 : a3) * di;

        int g = batch[node];
        if (g != gprev) {
            if (gprev >= 0) {
                atomicAdd(&g_q[gprev * HID + fbase + 0], r0);
                atomicAdd(&g_q[gprev * HID + fbase + 1], r1);
                atomicAdd(&g_q[gprev * HID + fbase + 2], r2);
                atomicAdd(&g_q[gprev * HID + fbase + 3], r3);
            }
            gprev = g; r0 = r1 = r2 = r3 = 0.f;
        }
        r0 += v0; r1 += v1; r2 += v2; r3 += v3;
    }
    if (gprev >= 0) {
        atomicAdd(&g_q[gprev * HID + fbase + 0], r0);
        atomicAdd(&g_q[gprev * HID + fbase + 1], r1);
        atomicAdd(&g_q[gprev * HID + fbase + 2], r2);
        atomicAdd(&g_q[gprev * HID + fbase + 3], r3);
    }
}

// out[g] = (q[g] @ Wc) / max(cnt,1) + bc
__global__ void k_final(float* __restrict__ out) {
    int g = blockIdx.x;
    int o = threadIdx.x;
    __shared__ float sp[HID];
    for (int k = o; k < HID; k += 32) sp[k] = g_q[g * HID + k];
    __syncthreads();
    float inv = 1.f / fmaxf(g_gcnt[g], 1.f);
    if (o < F_OUT) {
        float acc = 0.f;
#pragma unroll 8
        for (int k = 0; k < HID; k++) acc = fmaf(sp[k], g_Wc[k * F_OUT + o], acc);
        out[g * F_OUT + o] = acc * inv + g_bc[o];
    }
}

// ---------------- launch ----------------
extern "C" void kernel_launch(void* const* d_in, const int* in_sizes, int n_in,
                              void* d_out, int out_size) {
    const float* x    = (const float*)d_in[0];
    const int*   esrc = (const int*)d_in[1];
    const int*   edst = (const int*)d_in[2];
    const int*   batch= (const int*)d_in[3];
    const float* W1   = (const float*)d_in[4];
    const float* b1   = (const float*)d_in[5];
    const float* W2   = (const float*)d_in[6];
    const float* b2   = (const float*)d_in[7];
    const float* Wlin = (const float*)d_in[8];
    const float* blin = (const float*)d_in[9];
    float* out = (float*)d_out;

    k_init<<<512, 256>>>(W2, b2, Wlin, blin);
    k_count<<<512, 256>>>(edst, batch);
    k_scan1<<<SCAN_NBLK, 1024>>>();
    k_scan23<<<(N_NODES + 255) / 256, 256>>>();
    k_fill<<<1024, 256>>>(esrc, edst, x);
    k_layer1<<<(N_NODES + 127) / 128, 128>>>(W1, b1);
    k_aggpool<<<(N_NODES + 63) / 64, 256>>>(batch);
    k_final<<<NUM_GRAPHS, 32>>>(out);
}